// round 15
// baseline (speedup 1.0000x reference)
#include <cuda_runtime.h>
#include <cstdint>

typedef unsigned long long u64;

#define BATCH 32
#define HID   64
#define CHUNK 2048
#define LOGC  11

__device__ __forceinline__ u64 fma2(u64 a, u64 b, u64 c){
    u64 d; asm("fma.rn.f32x2 %0, %1, %2, %3;" : "=l"(d) : "l"(a), "l"(b), "l"(c)); return d;
}
__device__ __forceinline__ u64 add2(u64 a, u64 b){
    u64 d; asm("add.rn.f32x2 %0, %1, %2;" : "=l"(d) : "l"(a), "l"(b)); return d;
}
__device__ __forceinline__ u64 mul2(u64 a, u64 b){
    u64 d; asm("mul.rn.f32x2 %0, %1, %2;" : "=l"(d) : "l"(a), "l"(b)); return d;
}
__device__ __forceinline__ u64 pack2(float lo, float hi){
    u64 d; asm("mov.b64 %0, {%1, %2};" : "=l"(d) : "f"(lo), "f"(hi)); return d;
}
__device__ __forceinline__ float hsum2(u64 a){
    float lo, hi; asm("mov.b64 {%0,%1}, %2;" : "=f"(lo), "=f"(hi) : "l"(a)); return lo + hi;
}
__device__ __forceinline__ float ex2f(float a){
    float d; asm("ex2.approx.f32 %0, %1;" : "=f"(d) : "f"(a)); return d;
}
__device__ __forceinline__ float rcpf(float a){
    float d; asm("rcp.approx.f32 %0, %1;" : "=f"(d) : "f"(a)); return d;
}

#define NEG_L2E (-1.4426950408889634f)
#define TWO_L2E  2.8853900817779268f

// One CTA per batch row. 64 threads (2 warps); thread i owns hidden unit i
// COMPLETELY: full 64-wide r/z/n dots (96 FMA2, 6 interleaved accumulators),
// both sigmoids and the tanh thread-local. ZERO shuffles. 2-warp barrier
// (minimal skew). h loads are warp-uniform broadcasts, streamed (consumed
// per 16B load) to keep registers under the 255 ceiling:
// 192 weight regs + ~45 live. All R11/R12 machinery retained: pre-scaled
// weights, accumulators seeded with x/bias terms, single-FMA tail,
// 4-step unroll with hoisted x-terms, STS+STG tail.
__global__ void __launch_bounds__(64, 1)
gru_kernel(const float* __restrict__ x, const float* __restrict__ w_ih,
           const float* __restrict__ w_hh, const float* __restrict__ b_ih,
           const float* __restrict__ b_hh, float* __restrict__ states, int T)
{
    __shared__ __align__(16) float hbuf[2][HID];
    __shared__ __align__(16) float xs[2][CHUNK];

    const int tid = threadIdx.x;
    const int b   = blockIdx.x;
    const int i   = tid;               // hidden unit (0..63)

    // weights into registers, PRE-SCALED (packed f32x2)
    u64 wr[32], wz[32], wn[32];
    {
        const u64 sL = pack2(NEG_L2E, NEG_L2E);
        const u64 s2 = pack2(TWO_L2E, TWO_L2E);
        const u64* sr = (const u64*)(w_hh + (size_t)i * 64);
        const u64* sz = (const u64*)(w_hh + (size_t)(64 + i) * 64);
        const u64* sn = (const u64*)(w_hh + (size_t)(128 + i) * 64);
        #pragma unroll
        for (int q = 0; q < 32; q++) {
            wr[q] = mul2(sr[q], sL);
            wz[q] = mul2(sz[q], sL);
            wn[q] = mul2(sn[q], s2);
        }
    }

    // fused activation constants
    const float wihrL = w_ih[i] * NEG_L2E;
    const float crL   = (b_hh[i] + b_ih[i]) * NEG_L2E;
    const float wihzL = w_ih[64 + i] * NEG_L2E;
    const float czL   = (b_hh[64 + i] + b_ih[64 + i]) * NEG_L2E;
    const float wihn2 = w_ih[128 + i] * TWO_L2E;
    const float bihn2 = b_ih[128 + i] * TWO_L2E;
    const float bhhn2 = b_hh[128 + i] * TWO_L2E;

    const float* xrow = x + (size_t)b * T;

    hbuf[0][tid] = 0.0f;
    {
        const float4* src = (const float4*)xrow;
        float4* dst = (float4*)xs[0];
        #pragma unroll
        for (int q = 0; q < CHUNK / 4 / 64; q++) dst[tid + q * 64] = src[tid + q * 64];
    }
    __syncthreads();

    float* sp = states + ((size_t)b * T) * HID + i;
    float hprev = 0.0f;
    const int nch = T >> LOGC;

    // one GRU step; x-terms precomputed by caller
    auto step = [&](const float* hc, float* hd, float xrc, float xzc, float xn2) {
        const float hm1 = hprev - 1.0f;           // off-chain

        // seeded accumulators: reduce directly yields the ex2 arguments
        u64 r0 = pack2(xrc,   0.0f), r1 = 0;
        u64 z0 = pack2(xzc,   0.0f), z1 = 0;
        u64 n0 = pack2(bhhn2, 0.0f), n1 = 0;

        // stream h (warp-uniform broadcast LDS.128), consume immediately.
        // Accum reuse distance = 6 instructions >= FMA latency.
        const ulonglong2* hs = (const ulonglong2*)hc;
        #pragma unroll
        for (int q = 0; q < 8; q++) {
            ulonglong2 h0 = hs[2*q], h1 = hs[2*q+1];
            r0 = fma2(h0.x, wr[4*q],   r0);
            z0 = fma2(h0.x, wz[4*q],   z0);
            n0 = fma2(h0.x, wn[4*q],   n0);
            r1 = fma2(h0.y, wr[4*q+1], r1);
            z1 = fma2(h0.y, wz[4*q+1], z1);
            n1 = fma2(h0.y, wn[4*q+1], n1);
            r0 = fma2(h1.x, wr[4*q+2], r0);
            z0 = fma2(h1.x, wz[4*q+2], z0);
            n0 = fma2(h1.x, wn[4*q+2], n0);
            r1 = fma2(h1.y, wr[4*q+3], r1);
            z1 = fma2(h1.y, wz[4*q+3], z1);
            n1 = fma2(h1.y, wn[4*q+3], n1);
        }
        float gr  = rcpf(1.0f + ex2f(hsum2(add2(r0, r1))));   // sigma(r)
        float gz  = rcpf(1.0f + ex2f(hsum2(add2(z0, z1))));   // sigma(z)
        float hn2 = hsum2(add2(n0, n1));                      // 2log2e*hn

        // off-chain: A = 1 + z(h-1), gzm2 = 2z-2
        float A    = fmaf(gz, hm1, 1.0f);
        float gzm2 = fmaf(2.0f, gz, -2.0f);

        // chain: e2 -> R -> hnew -> STS -> bar
        float e2 = ex2f(fmaf(gr, hn2, xn2));
        float R  = rcpf(e2 + 1.0f);
        float hnew = fmaf(gzm2, R, A);                   // (1-z)tanh + z*h
        hprev = hnew;

        hd[i] = hnew;
        __stcs(sp, hnew);
        sp += HID;
        __syncthreads();
    };

    for (int c = 0; c < nch; c++) {
        if (c + 1 < nch) {  // prefetch next x chunk: one branch per 2048 steps
            const float4* src = (const float4*)(xrow + (size_t)(c + 1) * CHUNK);
            float4* dst = (float4*)xs[(c + 1) & 1];
            #pragma unroll
            for (int q = 0; q < CHUNK / 4 / 64; q++) dst[tid + q * 64] = src[tid + q * 64];
        }
        const float* xc = xs[c & 1];

        for (int tl = 0; tl < CHUNK; tl += 4) {
            // all four steps' x-terms up front (fill stall shadows)
            float xt0 = xc[tl],     xt1 = xc[tl + 1];
            float xt2 = xc[tl + 2], xt3 = xc[tl + 3];
            float xr0 = fmaf(xt0, wihrL, crL), xz0 = fmaf(xt0, wihzL, czL), xn0 = fmaf(xt0, wihn2, bihn2);
            float xr1 = fmaf(xt1, wihrL, crL), xz1 = fmaf(xt1, wihzL, czL), xn1 = fmaf(xt1, wihn2, bihn2);
            float xr2 = fmaf(xt2, wihrL, crL), xz2 = fmaf(xt2, wihzL, czL), xn2_ = fmaf(xt2, wihn2, bihn2);
            float xr3 = fmaf(xt3, wihrL, crL), xz3 = fmaf(xt3, wihzL, czL), xn3 = fmaf(xt3, wihn2, bihn2);

            step(hbuf[0], hbuf[1], xr0, xz0, xn0);
            step(hbuf[1], hbuf[0], xr1, xz1, xn1);
            step(hbuf[0], hbuf[1], xr2, xz2, xn2_);
            step(hbuf[1], hbuf[0], xr3, xz3, xn3);
        }
    }
}

// out[n] = dot(states[n,:], w_lin) + b_lin + x[n]
#define HROWS 128
#define HPAD  65
__global__ void __launch_bounds__(128, 4)
head_kernel(const float* __restrict__ st, const float* __restrict__ x,
            const float* __restrict__ wl, const float* __restrict__ bl,
            float* __restrict__ out, int BT)
{
    __shared__ float tile[HROWS * HPAD];
    __shared__ float wsh[HID];

    const int tid = threadIdx.x;
    const size_t row0 = (size_t)blockIdx.x * HROWS;

    if (tid < HID) wsh[tid] = wl[tid];

    const float4* src = (const float4*)(st + row0 * HID);
    #pragma unroll
    for (int q = 0; q < (HROWS * HID / 4) / 128; q++) {
        int f4 = tid + q * 128;
        float4 v = src[f4];
        int flat = f4 * 4;
        int r = flat >> 6;
        int c = flat & 63;
        float* drow = &tile[r * HPAD + c];
        drow[0] = v.x; drow[1] = v.y; drow[2] = v.z; drow[3] = v.w;
    }
    __syncthreads();

    const float* trow = &tile[tid * HPAD];
    float acc = 0.0f;
    #pragma unroll
    for (int k = 0; k < HID; k++) acc = fmaf(trow[k], wsh[k], acc);

    size_t n = row0 + tid;
    out[n] = acc + bl[0] + x[n];
}

extern "C" void kernel_launch(void* const* d_in, const int* in_sizes, int n_in,
                              void* d_out, int out_size)
{
    const float* x     = (const float*)d_in[0];
    const float* w_ih  = (const float*)d_in[1];
    const float* w_hh  = (const float*)d_in[2];
    const float* b_ih  = (const float*)d_in[3];
    const float* b_hh  = (const float*)d_in[4];
    const float* w_lin = (const float*)d_in[5];
    const float* b_lin = (const float*)d_in[6];

    float* out = (float*)d_out;
    const int BT = in_sizes[0];          // B * T
    const int T  = BT / BATCH;
    float* states = out + BT;            // d_out = [out | states]

    gru_kernel<<<BATCH, 64>>>(x, w_ih, w_hh, b_ih, b_hh, states, T);
    head_kernel<<<BT / HROWS, 128>>>(states, x, w_lin, b_lin, out, BT);
}

// round 16
// speedup vs baseline: 1.1262x; 1.1262x over previous
#include <cuda_runtime.h>
#include <cstdint>

typedef unsigned long long u64;

#define BATCH 32
#define HID   64
#define CHUNK 2048
#define LOGC  11

__device__ __forceinline__ u64 fma2(u64 a, u64 b, u64 c){
    u64 d; asm("fma.rn.f32x2 %0, %1, %2, %3;" : "=l"(d) : "l"(a), "l"(b), "l"(c)); return d;
}
__device__ __forceinline__ u64 add2(u64 a, u64 b){
    u64 d; asm("add.rn.f32x2 %0, %1, %2;" : "=l"(d) : "l"(a), "l"(b)); return d;
}
__device__ __forceinline__ u64 mul2(u64 a, u64 b){
    u64 d; asm("mul.rn.f32x2 %0, %1, %2;" : "=l"(d) : "l"(a), "l"(b)); return d;
}
__device__ __forceinline__ u64 pack2(float lo, float hi){
    u64 d; asm("mov.b64 %0, {%1, %2};" : "=l"(d) : "f"(lo), "f"(hi)); return d;
}
__device__ __forceinline__ float hsum2(u64 a){
    float lo, hi; asm("mov.b64 {%0,%1}, %2;" : "=f"(lo), "=f"(hi) : "l"(a)); return lo + hi;
}
__device__ __forceinline__ float ex2f(float a){
    float d; asm("ex2.approx.f32 %0, %1;" : "=f"(d) : "f"(a)); return d;
}
__device__ __forceinline__ float rcpf(float a){
    float d; asm("rcp.approx.f32 %0, %1;" : "=f"(d) : "f"(a)); return d;
}

#define NEG_L2E (-1.4426950408889634f)
#define TWO_L2E  2.8853900817779268f

// One CTA per batch row. 128 threads; pair (2i,2i+1) owns hidden unit i.
// Lane p=0: full 64-dot for r; p=1: full 64-dot for z; BOTH lanes: full
// 64-dot for n (duplicated: FMA issue hides in stall shadows; chain matters).
// Only z crosses lanes (shfl consumed at the final FMA, slack-hidden).
// R12 form (best known) with the unroll widened 4->8: the post-bar x-term
// precompute block is amortized over 8 steps, loop branches halved.
__global__ void __launch_bounds__(128, 1)
gru_kernel(const float* __restrict__ x, const float* __restrict__ w_ih,
           const float* __restrict__ w_hh, const float* __restrict__ b_ih,
           const float* __restrict__ b_hh, float* __restrict__ states, int T)
{
    __shared__ __align__(16) float hbuf[2][HID];
    __shared__ __align__(16) float xs[2][CHUNK];

    const int tid = threadIdx.x;
    const int b   = blockIdx.x;
    const int i   = tid >> 1;
    const int p   = tid & 1;
    const int ia  = i + 64 * p;        // r-row (p=0) or z-row (p=1)
    const int in_ = 128 + i;           // n-row

    // weights into registers, PRE-SCALED (packed f32x2)
    u64 wa[32];                         // own-gate row * (-log2e)
    {
        const u64 s = pack2(NEG_L2E, NEG_L2E);
        const u64* was = (const u64*)(w_hh + (size_t)ia * 64);
        #pragma unroll
        for (int q = 0; q < 32; q++) wa[q] = mul2(was[q], s);
    }
    u64 wn[32];                         // full n-row * (2*log2e)
    {
        const u64 s = pack2(TWO_L2E, TWO_L2E);
        const u64* wns = (const u64*)(w_hh + (size_t)in_ * 64);
        #pragma unroll
        for (int q = 0; q < 32; q++) wn[q] = mul2(wns[q], s);
    }

    // fused activation constants
    const float wihaL = w_ih[ia] * NEG_L2E;
    const float caL   = (b_hh[ia] + b_ih[ia]) * NEG_L2E;
    const float wihn2 = w_ih[in_] * TWO_L2E;
    const float bihn2 = b_ih[in_] * TWO_L2E;
    const float bhhn2 = b_hh[in_] * TWO_L2E;

    const float* xrow = x + (size_t)b * T;

    if (tid < HID) hbuf[0][tid] = 0.0f;
    {
        const float4* src = (const float4*)xrow;
        float4* dst = (float4*)xs[0];
        #pragma unroll
        for (int q = 0; q < CHUNK / 4 / 128; q++) dst[tid + q * 128] = src[tid + q * 128];
    }
    __syncthreads();

    float* sp = states + ((size_t)b * T) * HID + i;   // additive pointer
    float hprev = 0.0f;
    const int nch = T >> LOGC;
    const u64 nb0 = pack2(bhhn2, 0.0f);      // n-acc init (bias pre-added)

    // one GRU step; x-terms precomputed by caller
    auto step = [&](const float* hc, float* hd, float xac, float xn2) {
        const float hm1 = hprev - 1.0f;           // off-chain

        // load h once (16 x LDS.128), reuse for both dots
        ulonglong2 hv[16];
        const ulonglong2* hs = (const ulonglong2*)hc;
        #pragma unroll
        for (int q = 0; q < 16; q++) hv[q] = hs[q];

        // own-gate 64-dot; acc a0 seeded with xac -> reduce yields ex2 arg
        u64 a0 = pack2(xac, 0.0f);
        u64 a1=0,a2=0,a3=0,a4=0,a5=0,a6=0,a7=0;
        #pragma unroll
        for (int q = 0; q < 4; q++) {
            a0 = fma2(hv[4*q].x,   wa[8*q],   a0);
            a1 = fma2(hv[4*q].y,   wa[8*q+1], a1);
            a2 = fma2(hv[4*q+1].x, wa[8*q+2], a2);
            a3 = fma2(hv[4*q+1].y, wa[8*q+3], a3);
            a4 = fma2(hv[4*q+2].x, wa[8*q+4], a4);
            a5 = fma2(hv[4*q+2].y, wa[8*q+5], a5);
            a6 = fma2(hv[4*q+3].x, wa[8*q+6], a6);
            a7 = fma2(hv[4*q+3].y, wa[8*q+7], a7);
        }
        float argA = hsum2(add2(add2(add2(a0,a1),add2(a2,a3)),
                                add2(add2(a4,a5),add2(a6,a7))));
        float ga = rcpf(1.0f + ex2f(argA));              // sigma(own gate)
        float gz = __shfl_xor_sync(0xffffffffu, ga, 1);  // z for lane0 (slack)

        // n 64-dot (duplicated on both lanes); acc seeded with bias
        u64 n0 = nb0;
        u64 n1=0,n2=0,n3=0,n4=0,n5=0,n6=0,n7=0;
        #pragma unroll
        for (int q = 0; q < 4; q++) {
            n0 = fma2(hv[4*q].x,   wn[8*q],   n0);
            n1 = fma2(hv[4*q].y,   wn[8*q+1], n1);
            n2 = fma2(hv[4*q+1].x, wn[8*q+2], n2);
            n3 = fma2(hv[4*q+1].y, wn[8*q+3], n3);
            n4 = fma2(hv[4*q+2].x, wn[8*q+4], n4);
            n5 = fma2(hv[4*q+2].y, wn[8*q+5], n5);
            n6 = fma2(hv[4*q+3].x, wn[8*q+6], n6);
            n7 = fma2(hv[4*q+3].y, wn[8*q+7], n7);
        }
        float hn2 = hsum2(add2(add2(add2(n0,n1),add2(n2,n3)),
                               add2(add2(n4,n5),add2(n6,n7))));  // 2log2e*hn

        // off-chain (ready before R): A = 1 + z(h-1), gzm2 = 2z-2
        float A    = fmaf(gz, hm1, 1.0f);
        float gzm2 = fmaf(2.0f, gz, -2.0f);

        // chain: e2 -> R -> hnew (single FMA tail)
        float e2 = ex2f(fmaf(ga, hn2, xn2));
        float R  = rcpf(e2 + 1.0f);
        float hnew = fmaf(gzm2, R, A);                   // (1-z)tanh + z*h
        hprev = hnew;

        if (!p) {
            hd[i] = hnew;
            __stcs(sp, hnew);
        }
        sp += HID;
        __syncthreads();
    };

    for (int c = 0; c < nch; c++) {
        if (c + 1 < nch) {  // prefetch next x chunk: one branch per 2048 steps
            const float4* src = (const float4*)(xrow + (size_t)(c + 1) * CHUNK);
            float4* dst = (float4*)xs[(c + 1) & 1];
            #pragma unroll
            for (int q = 0; q < CHUNK / 4 / 128; q++) dst[tid + q * 128] = src[tid + q * 128];
        }
        const float* xc = xs[c & 1];

        for (int tl = 0; tl < CHUNK; tl += 8) {
            // all eight steps' x-terms up front (fill stall shadows)
            float xt0 = xc[tl],     xt1 = xc[tl + 1];
            float xt2 = xc[tl + 2], xt3 = xc[tl + 3];
            float xt4 = xc[tl + 4], xt5 = xc[tl + 5];
            float xt6 = xc[tl + 6], xt7 = xc[tl + 7];
            float xa0 = fmaf(xt0, wihaL, caL), xn0 = fmaf(xt0, wihn2, bihn2);
            float xa1 = fmaf(xt1, wihaL, caL), xn1 = fmaf(xt1, wihn2, bihn2);
            float xa2 = fmaf(xt2, wihaL, caL), xn2_ = fmaf(xt2, wihn2, bihn2);
            float xa3 = fmaf(xt3, wihaL, caL), xn3 = fmaf(xt3, wihn2, bihn2);
            float xa4 = fmaf(xt4, wihaL, caL), xn4 = fmaf(xt4, wihn2, bihn2);
            float xa5 = fmaf(xt5, wihaL, caL), xn5 = fmaf(xt5, wihn2, bihn2);
            float xa6 = fmaf(xt6, wihaL, caL), xn6 = fmaf(xt6, wihn2, bihn2);
            float xa7 = fmaf(xt7, wihaL, caL), xn7 = fmaf(xt7, wihn2, bihn2);

            step(hbuf[0], hbuf[1], xa0, xn0);
            step(hbuf[1], hbuf[0], xa1, xn1);
            step(hbuf[0], hbuf[1], xa2, xn2_);
            step(hbuf[1], hbuf[0], xa3, xn3);
            step(hbuf[0], hbuf[1], xa4, xn4);
            step(hbuf[1], hbuf[0], xa5, xn5);
            step(hbuf[0], hbuf[1], xa6, xn6);
            step(hbuf[1], hbuf[0], xa7, xn7);
        }
    }
}

// out[n] = dot(states[n,:], w_lin) + b_lin + x[n]
#define HROWS 128
#define HPAD  65
__global__ void __launch_bounds__(128, 4)
head_kernel(const float* __restrict__ st, const float* __restrict__ x,
            const float* __restrict__ wl, const float* __restrict__ bl,
            float* __restrict__ out, int BT)
{
    __shared__ float tile[HROWS * HPAD];
    __shared__ float wsh[HID];

    const int tid = threadIdx.x;
    const size_t row0 = (size_t)blockIdx.x * HROWS;

    if (tid < HID) wsh[tid] = wl[tid];

    const float4* src = (const float4*)(st + row0 * HID);
    #pragma unroll
    for (int q = 0; q < (HROWS * HID / 4) / 128; q++) {
        int f4 = tid + q * 128;
        float4 v = src[f4];
        int flat = f4 * 4;
        int r = flat >> 6;
        int c = flat & 63;
        float* drow = &tile[r * HPAD + c];
        drow[0] = v.x; drow[1] = v.y; drow[2] = v.z; drow[3] = v.w;
    }
    __syncthreads();

    const float* trow = &tile[tid * HPAD];
    float acc = 0.0f;
    #pragma unroll
    for (int k = 0; k < HID; k++) acc = fmaf(trow[k], wsh[k], acc);

    size_t n = row0 + tid;
    out[n] = acc + bl[0] + x[n];
}

extern "C" void kernel_launch(void* const* d_in, const int* in_sizes, int n_in,
                              void* d_out, int out_size)
{
    const float* x     = (const float*)d_in[0];
    const float* w_ih  = (const float*)d_in[1];
    const float* w_hh  = (const float*)d_in[2];
    const float* b_ih  = (const float*)d_in[3];
    const float* b_hh  = (const float*)d_in[4];
    const float* w_lin = (const float*)d_in[5];
    const float* b_lin = (const float*)d_in[6];

    float* out = (float*)d_out;
    const int BT = in_sizes[0];          // B * T
    const int T  = BT / BATCH;
    float* states = out + BT;            // d_out = [out | states]

    gru_kernel<<<BATCH, 128>>>(x, w_ih, w_hh, b_ih, b_hh, states, T);
    head_kernel<<<BT / HROWS, 128>>>(states, x, w_lin, b_lin, out, BT);
}